// round 4
// baseline (speedup 1.0000x reference)
#include <cuda_runtime.h>
#include <cstdint>
#include <cstddef>

// ---------------------------------------------------------------------------
// Persistent-register 2-layer GRU, half-row split. 16 clusters x 8 CTAs x 480.
// Each lane owns HALF a weight row (100 floats = 50 u64 regs):
//   tid   0-149 : W_hh0 half-rows (phase A, reads h0[p])
//   tid 150-299 : W_hh1 half-rows (phase A, reads h1[p])
//   tid 300-449 : W_ih1 half-rows (phase B, reads h0new)
//   tid 450-457 : W_fc  half-rows (FC pipelined 1 step behind)
//   tid 464-471 : x prefetch / input staging
// Dots go to local smem D[b][608] (column = tid) -> conflict-free STS; cell
// threads combine the two halves. Only h state crosses the cluster (DSMEM).
// ---------------------------------------------------------------------------

#define HDIM   200
#define TSTEPS 1024
#define NB     8
#define NTHR   480
#define CLSZ   8
#define HB     (NB*HDIM)      // 1600 floats per h parity buffer
#define DPITCH 608

typedef unsigned long long u64;

enum {
  O_D   = 0,                  // dots [8][608]
  O_H0  = O_D + 8*DPITCH,     // h0 [2][8][200]
  O_H1  = O_H0 + 2*HB,        // h1 [2][8][200]
  O_INB = O_H1 + 2*HB,        // inputs [8][8]
  O_WI0 = O_INB + 64,         // W_ih0 slice [3][25][8]
  O_B0  = O_WI0 + 600,        // layer0 biases: r[25], z[25], nx[25], nh[25]
  O_B1  = O_B0 + 100,         // layer1 biases: same
  O_BFC = O_B1 + 100,
  SMEM_F = O_BFC + 4          // 12132 floats = 48528 B (< 48 KB)
};

__shared__ float smem[SMEM_F];

#define FMA2(acc_, a_, b_) \
  asm("fma.rn.f32x2 %0, %1, %2, %0;" : "+l"(acc_) : "l"(a_), "l"(b_))
#define ADD2(d_, a_, b_) \
  asm("add.rn.f32x2 %0, %1, %2;" : "=l"(d_) : "l"(a_), "l"(b_))
#define PACK2(d_, x_, y_) \
  asm("mov.b64 %0, {%1, %2};" : "=l"(d_) : "f"(x_), "f"(y_))

__device__ __forceinline__ float red2(u64 v) {
  float lo, hi;
  asm("mov.b64 {%0,%1}, %2;" : "=f"(lo), "=f"(hi) : "l"(v));
  return lo + hi;
}
__device__ __forceinline__ void cluster_sync() {
  asm volatile("barrier.cluster.arrive.aligned;" ::: "memory");
  asm volatile("barrier.cluster.wait.aligned;" ::: "memory");
}
__device__ __forceinline__ float sigmoid_f(float x) {
  return __fdividef(1.0f, 1.0f + __expf(-x));
}
__device__ __forceinline__ float tanh_f(float x) {
  float e = __expf(-2.0f * x);
  return __fdividef(2.0f, 1.0f + e) - 1.0f;
}

// 8 batched 100-float dot products: w (50 u64 regs) . h[b][half*100 ..]
// voff already includes parity + half offset. Result -> D[b][dcol].
__device__ __forceinline__ void mv8(const u64* w, int voff, int dcol) {
  #pragma unroll 1
  for (int b = 0; b < NB; b++) {
    const ulonglong2* hv = (const ulonglong2*)(smem + voff + b*HDIM);
    u64 a0 = 0, a1 = 0, a2 = 0, a3 = 0;
    #pragma unroll
    for (int i = 0; i < 12; i++) {
      ulonglong2 A = hv[2*i], B = hv[2*i+1];
      FMA2(a0, w[4*i],   A.x);
      FMA2(a1, w[4*i+1], A.y);
      FMA2(a2, w[4*i+2], B.x);
      FMA2(a3, w[4*i+3], B.y);
    }
    { ulonglong2 A = hv[24]; FMA2(a0, w[48], A.x); FMA2(a1, w[49], A.y); }
    ADD2(a0, a0, a1); ADD2(a2, a2, a3); ADD2(a0, a0, a2);
    smem[O_D + b*DPITCH + dcol] = red2(a0);
  }
}

__global__ void __launch_bounds__(NTHR, 1) __cluster_dims__(CLSZ, 1, 1)
gru2_kernel(const float* __restrict__ x,
            const float* __restrict__ W_ih0, const float* __restrict__ W_hh0,
            const float* __restrict__ b_ih0, const float* __restrict__ b_hh0,
            const float* __restrict__ W_ih1, const float* __restrict__ W_hh1,
            const float* __restrict__ b_ih1, const float* __restrict__ b_hh1,
            const float* __restrict__ W_fc,  const float* __restrict__ b_fc,
            float* __restrict__ out)
{
  const int tid = threadIdx.x;
  uint32_t rank;
  asm("mov.u32 %0, %%cluster_ctarank;" : "=r"(rank));
  const int g = blockIdx.x >> 3;   // batch group (cluster id)
  uint32_t sb = (uint32_t)__cvta_generic_to_shared(smem);

  // ---- role resolution ----
  const float* wsrc = nullptr;
  int dcol = 0, half = 0;
  if (tid < 150) {
    int u = tid, row = u >> 1; half = u & 1;
    int gt = row / 25, jl = row % 25;
    wsrc = W_hh0 + (size_t)(gt*HDIM + (int)rank*25 + jl) * HDIM + half*100;
    dcol = u;
  } else if (tid < 300) {
    int u = tid - 150, row = u >> 1; half = u & 1;
    int gt = row / 25, jl = row % 25;
    wsrc = W_hh1 + (size_t)(gt*HDIM + (int)rank*25 + jl) * HDIM + half*100;
    dcol = 150 + u;
  } else if (tid < 450) {
    int u = tid - 300, row = u >> 1; half = u & 1;
    int gt = row / 25, jl = row % 25;
    wsrc = W_ih1 + (size_t)(gt*HDIM + (int)rank*25 + jl) * HDIM + half*100;
    dcol = 300 + u;
  } else if (tid < 458) {
    int u = tid - 450, o = u >> 1; half = u & 1;
    wsrc = W_fc + (size_t)o * HDIM + half*100;
    dcol = 600 + u;
  }

  // ---- load this lane's 100-float weight half-row into registers ----
  u64 w[50];
  if (wsrc) {
    #pragma unroll
    for (int i = 0; i < 25; i++) {
      float4 f = ((const float4*)wsrc)[i];
      PACK2(w[2*i],   f.x, f.y);
      PACK2(w[2*i+1], f.z, f.w);
    }
  } else {
    #pragma unroll
    for (int i = 0; i < 50; i++) w[i] = 0ull;
  }

  // ---- init smem ----
  for (int i = tid; i < 2*HB; i += NTHR) { smem[O_H0 + i] = 0.f; smem[O_H1 + i] = 0.f; }
  for (int i = tid; i < 600; i += NTHR)
    smem[O_WI0 + i] = W_ih0[(size_t)((i/200)*HDIM + (int)rank*25) * 8 + (i % 200)];
  if (tid < 25) {
    int J = (int)rank*25 + tid;
    smem[O_B0 +      tid] = b_ih0[J]        + b_hh0[J];
    smem[O_B0 + 25 + tid] = b_ih0[HDIM+J]   + b_hh0[HDIM+J];
    smem[O_B0 + 50 + tid] = b_ih0[2*HDIM+J];
    smem[O_B0 + 75 + tid] = b_hh0[2*HDIM+J];
    smem[O_B1 +      tid] = b_ih1[J]        + b_hh1[J];
    smem[O_B1 + 25 + tid] = b_ih1[HDIM+J]   + b_hh1[HDIM+J];
    smem[O_B1 + 50 + tid] = b_ih1[2*HDIM+J];
    smem[O_B1 + 75 + tid] = b_hh1[2*HDIM+J];
  }
  if (tid < 4) smem[O_BFC + tid] = b_fc[tid];
  if (tid >= 464 && tid < 472) {
    int xb = tid - 464;
    const float* xr = x + (size_t)(g*NB + xb) * TSTEPS * 8;
    float* ib = smem + O_INB + xb*8;
    ib[0] = 1.f; ib[1] = 1.f; ib[2] = 1.f; ib[3] = 1.f;
    ib[4] = xr[4]; ib[5] = xr[5]; ib[6] = xr[6]; ib[7] = xr[7];
  }
  cluster_sync();

  for (int t = 0; t < TSTEPS; t++) {
    const int p = t & 1, q = p ^ 1;

    // ===== W1: layer0-h and layer1-h matvecs on h[p]; FC(t-1); x prefetch
    float4 xnext = make_float4(0.f, 0.f, 0.f, 0.f);
    if (tid >= 464 && tid < 472)
      xnext = *(const float4*)(x + ((size_t)(g*NB + (tid-464)) * TSTEPS + t) * 8);

    if (tid < 150) {
      mv8(w, O_H0 + p*HB + half*100, dcol);
    } else if (tid < 300) {
      mv8(w, O_H1 + p*HB + half*100, dcol);
    } else if (tid >= 450 && tid < 458 && t > 0) {
      // FC partial on h1[p] (state after step t-1), batch = rank
      const ulonglong2* hv =
          (const ulonglong2*)(smem + O_H1 + p*HB + (int)rank*HDIM + half*100);
      u64 a0 = 0, a1 = 0;
      #pragma unroll
      for (int i = 0; i < 25; i++) {
        ulonglong2 A = hv[i];
        FMA2(a0, w[2*i], A.x); FMA2(a1, w[2*i+1], A.y);
      }
      ADD2(a0, a0, a1);
      smem[O_D + dcol] = red2(a0);   // D[0][600+u]
    }
    __syncthreads();

    // ===== W2: cell0 update + cluster broadcast of h0new; FC combine
    if (tid < 200) {
      int jl = tid >> 3, b = tid & 7;
      int gj = (int)rank*25 + jl;
      const float* Db = smem + O_D + b*DPITCH;
      float2 pr = *(const float2*)(Db + jl*2);
      float2 pz = *(const float2*)(Db + 50 + jl*2);
      float2 pn = *(const float2*)(Db + 100 + jl*2);
      float dr = pr.x + pr.y, dz = pz.x + pz.y, dn = pn.x + pn.y;
      float xr = smem[O_B0 + jl], xz = smem[O_B0 + 25 + jl], xn = smem[O_B0 + 50 + jl];
      #pragma unroll
      for (int c = 0; c < 8; c++) {
        float ic = smem[O_INB + b*8 + c];
        xr = fmaf(smem[O_WI0 +       jl*8 + c], ic, xr);
        xz = fmaf(smem[O_WI0 + 200 + jl*8 + c], ic, xz);
        xn = fmaf(smem[O_WI0 + 400 + jl*8 + c], ic, xn);
      }
      float r = sigmoid_f(xr + dr);
      float z = sigmoid_f(xz + dz);
      float n = tanh_f(xn + r * (dn + smem[O_B0 + 75 + jl]));
      float h_o = smem[O_H0 + p*HB + b*HDIM + gj];
      float hn = n + z * (h_o - n);
      uint32_t la = sb + (uint32_t)(O_H0 + q*HB + b*HDIM + gj) * 4;
      #pragma unroll
      for (int rr = 0; rr < CLSZ; rr++) {
        uint32_t ra;
        asm("mapa.shared::cluster.u32 %0, %1, %2;" : "=r"(ra) : "r"(la), "r"(rr));
        asm volatile("st.shared::cluster.f32 [%0], %1;" :: "r"(ra), "f"(hn) : "memory");
      }
    } else if (tid >= 200 && tid < 204 && t > 0) {
      int o = tid - 200;
      float2 pf = *(const float2*)(smem + O_D + 600 + o*2);
      float v = tanh_f(pf.x + pf.y + smem[O_BFC + o]);
      out[((size_t)(g*NB + (int)rank) * TSTEPS + (t-1)) * 4 + o] = v;
    }
    cluster_sync();   // h0new visible cluster-wide

    // ===== W3: layer1-x matvec on h0new; stage next inputs
    if (tid >= 300 && tid < 450)
      mv8(w, O_H0 + q*HB + half*100, dcol);
    if (tid >= 464 && tid < 472) {
      float* ib = smem + O_INB + (tid-464)*8;
      ib[0] = xnext.x; ib[1] = xnext.y; ib[2] = xnext.z; ib[3] = xnext.w;
    }
    __syncthreads();

    // ===== W4: cell1 update + cluster broadcast of h1new
    if (tid < 200) {
      int jl = tid >> 3, b = tid & 7;
      int gj = (int)rank*25 + jl;
      const float* Db = smem + O_D + b*DPITCH;
      float2 hr2 = *(const float2*)(Db + 150 + jl*2);
      float2 hz2 = *(const float2*)(Db + 200 + jl*2);
      float2 hn2 = *(const float2*)(Db + 250 + jl*2);
      float2 xr2 = *(const float2*)(Db + 300 + jl*2);
      float2 xz2 = *(const float2*)(Db + 350 + jl*2);
      float2 xn2 = *(const float2*)(Db + 400 + jl*2);
      float r  = sigmoid_f(xr2.x + xr2.y + hr2.x + hr2.y + smem[O_B1 + jl]);
      float z  = sigmoid_f(xz2.x + xz2.y + hz2.x + hz2.y + smem[O_B1 + 25 + jl]);
      float n  = tanh_f(xn2.x + xn2.y + smem[O_B1 + 50 + jl] +
                        r * (hn2.x + hn2.y + smem[O_B1 + 75 + jl]));
      float h_o = smem[O_H1 + p*HB + b*HDIM + gj];
      float hn = n + z * (h_o - n);
      uint32_t la = sb + (uint32_t)(O_H1 + q*HB + b*HDIM + gj) * 4;
      #pragma unroll
      for (int rr = 0; rr < CLSZ; rr++) {
        uint32_t ra;
        asm("mapa.shared::cluster.u32 %0, %1, %2;" : "=r"(ra) : "r"(la), "r"(rr));
        asm volatile("st.shared::cluster.f32 [%0], %1;" :: "r"(ra), "f"(hn) : "memory");
      }
    }
    cluster_sync();   // h1new visible cluster-wide
  }

  // ---- drain: FC for t = 1023 (final h1 in parity 0) ----
  if (tid >= 450 && tid < 458) {
    const ulonglong2* hv =
        (const ulonglong2*)(smem + O_H1 + (int)rank*HDIM + half*100);
    u64 a0 = 0, a1 = 0;
    #pragma unroll
    for (int i = 0; i < 25; i++) {
      ulonglong2 A = hv[i];
      FMA2(a0, w[2*i], A.x); FMA2(a1, w[2*i+1], A.y);
    }
    ADD2(a0, a0, a1);
    smem[O_D + dcol] = red2(a0);
  }
  __syncthreads();
  if (tid >= 200 && tid < 204) {
    int o = tid - 200;
    float2 pf = *(const float2*)(smem + O_D + 600 + o*2);
    float v = tanh_f(pf.x + pf.y + smem[O_BFC + o]);
    out[((size_t)(g*NB + (int)rank) * TSTEPS + (TSTEPS-1)) * 4 + o] = v;
  }
}

extern "C" void kernel_launch(void* const* d_in, const int* in_sizes, int n_in,
                              void* d_out, int out_size) {
  (void)in_sizes; (void)n_in; (void)out_size;
  const float* x     = (const float*)d_in[0];
  const float* W_ih0 = (const float*)d_in[1];
  const float* W_hh0 = (const float*)d_in[2];
  const float* b_ih0 = (const float*)d_in[3];
  const float* b_hh0 = (const float*)d_in[4];
  const float* W_ih1 = (const float*)d_in[5];
  const float* W_hh1 = (const float*)d_in[6];
  const float* b_ih1 = (const float*)d_in[7];
  const float* b_hh1 = (const float*)d_in[8];
  const float* W_fc  = (const float*)d_in[9];
  const float* b_fc  = (const float*)d_in[10];

  gru2_kernel<<<128, NTHR>>>(x, W_ih0, W_hh0, b_ih0, b_hh0,
                             W_ih1, W_hh1, b_ih1, b_hh1,
                             W_fc, b_fc, (float*)d_out);
}

// round 6
// speedup vs baseline: 1.0751x; 1.0751x over previous
#include <cuda_runtime.h>
#include <cstdint>
#include <cstddef>

// ---------------------------------------------------------------------------
// Pipelined 2-layer GRU: ONE cluster sync per step.
// Invariant at iteration i: smem h[parity p=i&1] holds pairs
//   {h0^(i)[k], h1^(i-1)[k]}  (h0^(i) = h0 after ref-step i-1).
// Iteration i:
//   matvec: a2[g] (f32x2) accumulates BOTH Whh0.h0 (lo) and Whh1.h1 (hi)
//           via interleaved weights; scalar accs do Wih1.h0. FC emits out_{i-2}.
//   cells : cell0 -> h0^(i+1) (ref step i L0), cell1 -> h1^(i) (ref step i-1 L1)
//   push  : ONE st.shared::cluster.b64 {h0n,h1n} per target CTA (8B).
//   cluster_sync.
// 16 clusters x 8 CTAs x 448 thr. Weights smem-resident (226.7 KB dynamic).
// ---------------------------------------------------------------------------

#define HDIM   200
#define TSTEPS 1024
#define NB     8
#define NTHR   448
#define CLSZ   8
#define TITER  (TSTEPS + 2)

typedef unsigned long long u64;

// float offsets
enum {
  O_W01 = 0,          // [3][25][400] interleaved {Whh0[k], Whh1[k]}
  O_WM2 = 30000,      // [3][25][200] Wih1
  O_WFC = 45000,      // [4][200]
  O_WI0 = 45800,      // [3][25][8]
  O_B0  = 46400,      // [4][25]: r(comb), z(comb), nx(ih), nh(hh)
  O_B1  = 46500,      // same for layer 1
  O_BFC = 46600,      // [4]
  O_INB = 46608,      // [8][8]
  O_H   = 46672,      // [2][8][400] pairs {h0,h1}  (16B aligned)
  O_DP  = 53072,      // u64[3][2][200] (= 2400 floats, 8B aligned)
  O_DS  = 55472,      // float[3][2][200]
  SMEM_F = 56672      // 226,688 bytes
};
#define SMEM_BYTES (SMEM_F*4)

#define FMA2(acc_, a_, b_) \
  asm("fma.rn.f32x2 %0, %1, %2, %0;" : "+l"(acc_) : "l"(a_), "l"(b_))
#define PACK2(d_, x_, y_) \
  asm("mov.b64 %0, {%1, %2};" : "=l"(d_) : "f"(x_), "f"(y_))
#define UNPK2(lo_, hi_, v_) \
  asm("mov.b64 {%0,%1}, %2;" : "=f"(lo_), "=f"(hi_) : "l"(v_))

__device__ __forceinline__ void cluster_sync() {
  asm volatile("barrier.cluster.arrive.aligned;" ::: "memory");
  asm volatile("barrier.cluster.wait.aligned;" ::: "memory");
}
__device__ __forceinline__ float sigmoid_f(float x) {
  return __fdividef(1.0f, 1.0f + __expf(-x));
}
__device__ __forceinline__ float tanh_f(float x) {
  float e = __expf(-2.0f * x);
  return __fdividef(2.0f, 1.0f + e) - 1.0f;
}

extern __shared__ float smem[];

__global__ void __launch_bounds__(NTHR, 1) __cluster_dims__(CLSZ, 1, 1)
gru2_kernel(const float* __restrict__ x,
            const float* __restrict__ W_ih0, const float* __restrict__ W_hh0,
            const float* __restrict__ b_ih0, const float* __restrict__ b_hh0,
            const float* __restrict__ W_ih1, const float* __restrict__ W_hh1,
            const float* __restrict__ b_ih1, const float* __restrict__ b_hh1,
            const float* __restrict__ W_fc,  const float* __restrict__ b_fc,
            float* __restrict__ out)
{
  const int tid = threadIdx.x;
  uint32_t rank;
  asm("mov.u32 %0, %%cluster_ctarank;" : "=r"(rank));
  const int g = blockIdx.x >> 3;
  uint32_t sb = (uint32_t)__cvta_generic_to_shared(smem);

  // ================= init =================
  for (int idx = tid; idx < 15000; idx += NTHR) {
    int row = idx / HDIM;          // g*25 + j
    int k   = idx % HDIM;
    int gt = row / 25, j = row % 25;
    size_t grow = (size_t)(gt*HDIM + (int)rank*25 + j);
    smem[O_W01 + row*400 + 2*k]     = W_hh0[grow*HDIM + k];
    smem[O_W01 + row*400 + 2*k + 1] = W_hh1[grow*HDIM + k];
    smem[O_WM2 + row*HDIM + k]      = W_ih1[grow*HDIM + k];
  }
  for (int idx = tid; idx < 800; idx += NTHR) smem[O_WFC + idx] = W_fc[idx];
  for (int idx = tid; idx < 600; idx += NTHR) {
    int row = idx >> 3, c = idx & 7;
    int gt = row / 25, j = row % 25;
    smem[O_WI0 + idx] = W_ih0[(size_t)(gt*HDIM + (int)rank*25 + j)*8 + c];
  }
  if (tid < 25) {
    int J = (int)rank*25 + tid;
    smem[O_B0 +      tid] = b_ih0[J]          + b_hh0[J];
    smem[O_B0 + 25 + tid] = b_ih0[HDIM + J]   + b_hh0[HDIM + J];
    smem[O_B0 + 50 + tid] = b_ih0[2*HDIM + J];
    smem[O_B0 + 75 + tid] = b_hh0[2*HDIM + J];
    smem[O_B1 +      tid] = b_ih1[J]          + b_hh1[J];
    smem[O_B1 + 25 + tid] = b_ih1[HDIM + J]   + b_hh1[HDIM + J];
    smem[O_B1 + 50 + tid] = b_ih1[2*HDIM + J];
    smem[O_B1 + 75 + tid] = b_hh1[2*HDIM + J];
  }
  if (tid < 4) smem[O_BFC + tid] = b_fc[tid];
  for (int idx = tid; idx < 2*NB*400; idx += NTHR) smem[O_H + idx] = 0.f;
  if (tid >= 432 && tid < 440) {
    int b = tid - 432;
    const float* xr = x + (size_t)(g*NB + b) * TSTEPS * 8;
    float* ib = smem + O_INB + b*8;
    ib[0] = 1.f; ib[1] = 1.f; ib[2] = 1.f; ib[3] = 1.f;
    ib[4] = xr[4]; ib[5] = xr[5]; ib[6] = xr[6]; ib[7] = xr[7];
  }
  cluster_sync();

  float4 xnext = make_float4(0.f, 0.f, 0.f, 0.f);

  for (int i = 0; i < TITER; i++) {
    const int p = i & 1, q = p ^ 1;

    // -- stage inputs for ref-step i (from prefetch at i-1), prefetch next --
    if (tid >= 432 && tid < 440) {
      int b = tid - 432;
      if (i > 0) {
        float* ib = smem + O_INB + b*8;
        ib[0] = xnext.x; ib[1] = xnext.y; ib[2] = xnext.z; ib[3] = xnext.w;
      }
      if (i < TSTEPS)
        xnext = *(const float4*)(x + ((size_t)(g*NB + b) * TSTEPS + i) * 8);
    }

    // ================= matvec phase =================
    if (tid < 400 && i <= TSTEPS) {
      const int u = tid % 200, half = tid / 200;
      const int j = u >> 3, b = u & 7;
      const float* hb  = smem + O_H + p*3200 + b*400 + half*200;
      const float* w0r = smem + O_W01 + (     j)*400 + half*200;
      const float* w0z = smem + O_W01 + (25 + j)*400 + half*200;
      const float* w0n = smem + O_W01 + (50 + j)*400 + half*200;
      const float* m2r = smem + O_WM2 + (     j)*200 + half*100;
      const float* m2z = smem + O_WM2 + (25 + j)*200 + half*100;
      const float* m2n = smem + O_WM2 + (50 + j)*200 + half*100;
      u64 a2r = 0, a2z = 0, a2n = 0;
      float sr = 0.f, sz = 0.f, sn = 0.f;
      #pragma unroll
      for (int c = 0; c < 25; c++) {
        const int kk = c*4;
        float4 A = *(const float4*)(hb + 2*kk);       // {h0,h1,h0,h1} k,k+1
        float4 B = *(const float4*)(hb + 2*kk + 4);   // k+2,k+3
        u64 pA0, pA1, pB0, pB1;
        PACK2(pA0, A.x, A.y); PACK2(pA1, A.z, A.w);
        PACK2(pB0, B.x, B.y); PACK2(pB1, B.z, B.w);
        u64 w0, w1;
        float4 W;
        W = *(const float4*)(w0r + 2*kk);     PACK2(w0, W.x, W.y); PACK2(w1, W.z, W.w);
        FMA2(a2r, w0, pA0); FMA2(a2r, w1, pA1);
        W = *(const float4*)(w0r + 2*kk + 4); PACK2(w0, W.x, W.y); PACK2(w1, W.z, W.w);
        FMA2(a2r, w0, pB0); FMA2(a2r, w1, pB1);
        W = *(const float4*)(w0z + 2*kk);     PACK2(w0, W.x, W.y); PACK2(w1, W.z, W.w);
        FMA2(a2z, w0, pA0); FMA2(a2z, w1, pA1);
        W = *(const float4*)(w0z + 2*kk + 4); PACK2(w0, W.x, W.y); PACK2(w1, W.z, W.w);
        FMA2(a2z, w0, pB0); FMA2(a2z, w1, pB1);
        W = *(const float4*)(w0n + 2*kk);     PACK2(w0, W.x, W.y); PACK2(w1, W.z, W.w);
        FMA2(a2n, w0, pA0); FMA2(a2n, w1, pA1);
        W = *(const float4*)(w0n + 2*kk + 4); PACK2(w0, W.x, W.y); PACK2(w1, W.z, W.w);
        FMA2(a2n, w0, pB0); FMA2(a2n, w1, pB1);
        float4 V;
        V = *(const float4*)(m2r + kk);
        sr = fmaf(V.x, A.x, sr); sr = fmaf(V.y, A.z, sr);
        sr = fmaf(V.z, B.x, sr); sr = fmaf(V.w, B.z, sr);
        V = *(const float4*)(m2z + kk);
        sz = fmaf(V.x, A.x, sz); sz = fmaf(V.y, A.z, sz);
        sz = fmaf(V.z, B.x, sz); sz = fmaf(V.w, B.z, sz);
        V = *(const float4*)(m2n + kk);
        sn = fmaf(V.x, A.x, sn); sn = fmaf(V.y, A.z, sn);
        sn = fmaf(V.z, B.x, sn); sn = fmaf(V.w, B.z, sn);
      }
      u64* Dp = (u64*)(smem + O_DP);
      Dp[      half*200 + u] = a2r;
      Dp[400 + half*200 + u] = a2z;
      Dp[800 + half*200 + u] = a2n;
      float* Ds = smem + O_DS;
      Ds[      half*200 + u] = sr;
      Ds[400 + half*200 + u] = sz;
      Ds[800 + half*200 + u] = sn;
    } else if (tid >= 400 && tid < 404 && i >= 2) {
      // ---- FC: out_{i-2} = tanh(Wfc @ h1^{(i-1)}), 4 (o,b) pairs per CTA
      int pidx = (int)rank*4 + (tid - 400);
      int o = pidx >> 3, b = pidx & 7;
      const float* wf = smem + O_WFC + o*200;
      const float* hv = smem + O_H + p*3200 + b*400;
      float a0 = 0.f, a1 = 0.f, a2 = 0.f, a3 = 0.f;
      #pragma unroll 10
      for (int k = 0; k < 200; k += 4) {
        a0 = fmaf(wf[k],   hv[2*k+1], a0);
        a1 = fmaf(wf[k+1], hv[2*k+3], a1);
        a2 = fmaf(wf[k+2], hv[2*k+5], a2);
        a3 = fmaf(wf[k+3], hv[2*k+7], a3);
      }
      float v = tanh_f(a0 + a1 + a2 + a3 + smem[O_BFC + o]);
      out[((size_t)(g*NB + b) * TSTEPS + (i-2)) * 4 + o] = v;
    }
    __syncthreads();

    // ================= cell phase + paired push =================
    if (tid < 200 && i <= TSTEPS) {
      const int j = tid >> 3, b = tid & 7;
      const int gj = (int)rank*25 + j;
      const u64* Dp = (const u64*)(smem + O_DP);
      const float* Ds = smem + O_DS;
      float r0a, r0b, z0a, z0b, n0a, n0b;
      float r1a, r1b, z1a, z1b, n1a, n1b;
      UNPK2(r0a, r1a, Dp[      tid]); UNPK2(r0b, r1b, Dp[200 + tid]);
      UNPK2(z0a, z1a, Dp[400 + tid]); UNPK2(z0b, z1b, Dp[600 + tid]);
      UNPK2(n0a, n1a, Dp[800 + tid]); UNPK2(n0b, n1b, Dp[1000 + tid]);
      float h0n = 0.f, h1n = 0.f;
      if (i < TSTEPS) {
        // cell0: ref-step i layer 0 -> h0^(i+1)
        float xr = smem[O_B0 + j], xz = smem[O_B0 + 25 + j], xn = smem[O_B0 + 50 + j];
        #pragma unroll
        for (int c = 0; c < 8; c++) {
          float ic = smem[O_INB + b*8 + c];
          xr = fmaf(smem[O_WI0 +       j*8 + c], ic, xr);
          xz = fmaf(smem[O_WI0 + 200 + j*8 + c], ic, xz);
          xn = fmaf(smem[O_WI0 + 400 + j*8 + c], ic, xn);
        }
        float r = sigmoid_f(xr + r0a + r0b);
        float z = sigmoid_f(xz + z0a + z0b);
        float n = tanh_f(xn + r * (n0a + n0b + smem[O_B0 + 75 + j]));
        float h_o = smem[O_H + p*3200 + b*400 + gj*2];
        h0n = n + z * (h_o - n);
      }
      if (i >= 1) {
        // cell1: ref-step i-1 layer 1 -> h1^(i)
        float dsr = Ds[tid] + Ds[200 + tid];
        float dsz = Ds[400 + tid] + Ds[600 + tid];
        float dsn = Ds[800 + tid] + Ds[1000 + tid];
        float r = sigmoid_f(dsr + r1a + r1b + smem[O_B1 + j]);
        float z = sigmoid_f(dsz + z1a + z1b + smem[O_B1 + 25 + j]);
        float n = tanh_f(dsn + smem[O_B1 + 50 + j] +
                         r * (n1a + n1b + smem[O_B1 + 75 + j]));
        float h_o = smem[O_H + p*3200 + b*400 + gj*2 + 1];
        h1n = n + z * (h_o - n);
      }
      u64 pv; PACK2(pv, h0n, h1n);
      uint32_t la = sb + (uint32_t)(O_H + q*3200 + b*400 + gj*2) * 4;
      #pragma unroll
      for (int rr = 0; rr < CLSZ; rr++) {
        uint32_t ra;
        asm("mapa.shared::cluster.u32 %0, %1, %2;" : "=r"(ra) : "r"(la), "r"(rr));
        asm volatile("st.shared::cluster.b64 [%0], %1;" :: "r"(ra), "l"(pv) : "memory");
      }
    }
    cluster_sync();
  }
}

extern "C" void kernel_launch(void* const* d_in, const int* in_sizes, int n_in,
                              void* d_out, int out_size) {
  (void)in_sizes; (void)n_in; (void)out_size;
  const float* x     = (const float*)d_in[0];
  const float* W_ih0 = (const float*)d_in[1];
  const float* W_hh0 = (const float*)d_in[2];
  const float* b_ih0 = (const float*)d_in[3];
  const float* b_hh0 = (const float*)d_in[4];
  const float* W_ih1 = (const float*)d_in[5];
  const float* W_hh1 = (const float*)d_in[6];
  const float* b_ih1 = (const float*)d_in[7];
  const float* b_hh1 = (const float*)d_in[8];
  const float* W_fc  = (const float*)d_in[9];
  const float* b_fc  = (const float*)d_in[10];

  cudaFuncSetAttribute(gru2_kernel,
                       cudaFuncAttributeMaxDynamicSharedMemorySize, SMEM_BYTES);
  gru2_kernel<<<128, NTHR, SMEM_BYTES>>>(x, W_ih0, W_hh0, b_ih0, b_hh0,
                                         W_ih1, W_hh1, b_ih1, b_hh1,
                                         W_fc, b_fc, (float*)d_out);
}

// round 7
// speedup vs baseline: 1.4385x; 1.3380x over previous
#include <cuda_runtime.h>
#include <cstdint>
#include <cstddef>

// ---------------------------------------------------------------------------
// Fully-fused pipelined 2-layer GRU. 16 clusters x 8 CTAs x 448 threads.
// Thread (j,b,half) computes half-K partial dots for ALL SIX gate dots of its
// (j,b): pair stream {Whh0,Whh1}x{h0,h1} (f32x2, direct ulonglong2 loads) and
// scalar stream Wih1 x h0 (from a locally-derived h0 copy). Halves combine
// in-warp via shfl.bfly(8); the SAME thread runs cell0+cell1 and pushes one
// 8B {h0n,h1n} pair to all 8 CTAs. ONE cluster sync per step.
// Pipeline invariant at iter i: pairs[p=i&1] = {h0^(i), h1^(i-1)}.
// ---------------------------------------------------------------------------

#define HDIM   200
#define TSTEPS 1024
#define NB     8
#define NTHR   448
#define CLSZ   8
#define TITER  (TSTEPS + 2)
#define PITCHP 420
#define HPAR   (NB*PITCHP)      // 3360 floats per pair-parity

typedef unsigned long long u64;

enum {
  O_W01 = 0,                    // [3][25][400] interleaved {Whh0[k],Whh1[k]}
  O_WM2 = 30000,                // [3][25][200] Wih1
  O_WFC = 45000,                // [4][200]
  O_WI0 = 45800,                // [3][25][8]
  O_B0  = 46400,                // [4][25]: r(comb), z(comb), nx, nh
  O_B1  = 46500,
  O_BFC = 46600,                // [4]
  O_INB = 46608,                // [8][8]
  O_H   = 46672,                // [2][8][PITCHP] pairs {h0,h1}
  O_H0C = O_H + 2*HPAR,         // [2][8][200] h0 scalar copy
  SMEM_F = O_H0C + 2*NB*HDIM    // 56592 floats = 226368 B
};
#define SMEM_BYTES (SMEM_F*4)

#define FMA2(acc_, a_, b_) \
  asm("fma.rn.f32x2 %0, %1, %2, %0;" : "+l"(acc_) : "l"(a_), "l"(b_))
#define PACK2(d_, x_, y_) \
  asm("mov.b64 %0, {%1, %2};" : "=l"(d_) : "f"(x_), "f"(y_))
#define UNPK2(lo_, hi_, v_) \
  asm("mov.b64 {%0,%1}, %2;" : "=f"(lo_), "=f"(hi_) : "l"(v_))

__device__ __forceinline__ void cluster_sync() {
  asm volatile("barrier.cluster.arrive.aligned;" ::: "memory");
  asm volatile("barrier.cluster.wait.aligned;" ::: "memory");
}
__device__ __forceinline__ float sigmoid_f(float x) {
  return __fdividef(1.0f, 1.0f + __expf(-x));
}
__device__ __forceinline__ float tanh_f(float x) {
  float e = __expf(-2.0f * x);
  return __fdividef(2.0f, 1.0f + e) - 1.0f;
}

extern __shared__ float smem[];

__global__ void __launch_bounds__(NTHR, 1) __cluster_dims__(CLSZ, 1, 1)
gru2_kernel(const float* __restrict__ x,
            const float* __restrict__ W_ih0, const float* __restrict__ W_hh0,
            const float* __restrict__ b_ih0, const float* __restrict__ b_hh0,
            const float* __restrict__ W_ih1, const float* __restrict__ W_hh1,
            const float* __restrict__ b_ih1, const float* __restrict__ b_hh1,
            const float* __restrict__ W_fc,  const float* __restrict__ b_fc,
            float* __restrict__ out)
{
  const int tid = threadIdx.x;
  uint32_t rank;
  asm("mov.u32 %0, %%cluster_ctarank;" : "=r"(rank));
  const int g = blockIdx.x >> 3;
  uint32_t sb = (uint32_t)__cvta_generic_to_shared(smem);

  // ================= init =================
  for (int idx = tid; idx < 15000; idx += NTHR) {
    int row = idx / HDIM;                       // gt*25 + j  (75 rows)
    int k   = idx % HDIM;
    int gt = row / 25, j = row % 25;
    size_t grow = (size_t)(gt*HDIM + (int)rank*25 + j);
    smem[O_W01 + row*400 + 2*k]     = W_hh0[grow*HDIM + k];
    smem[O_W01 + row*400 + 2*k + 1] = W_hh1[grow*HDIM + k];
    smem[O_WM2 + row*HDIM + k]      = W_ih1[grow*HDIM + k];
  }
  for (int idx = tid; idx < 800; idx += NTHR) smem[O_WFC + idx] = W_fc[idx];
  for (int idx = tid; idx < 600; idx += NTHR) {
    int row = idx >> 3, c = idx & 7;
    int gt = row / 25, j = row % 25;
    smem[O_WI0 + idx] = W_ih0[(size_t)(gt*HDIM + (int)rank*25 + j)*8 + c];
  }
  if (tid < 25) {
    int J = (int)rank*25 + tid;
    smem[O_B0 +      tid] = b_ih0[J]          + b_hh0[J];
    smem[O_B0 + 25 + tid] = b_ih0[HDIM + J]   + b_hh0[HDIM + J];
    smem[O_B0 + 50 + tid] = b_ih0[2*HDIM + J];
    smem[O_B0 + 75 + tid] = b_hh0[2*HDIM + J];
    smem[O_B1 +      tid] = b_ih1[J]          + b_hh1[J];
    smem[O_B1 + 25 + tid] = b_ih1[HDIM + J]   + b_hh1[HDIM + J];
    smem[O_B1 + 50 + tid] = b_ih1[2*HDIM + J];
    smem[O_B1 + 75 + tid] = b_hh1[2*HDIM + J];
  }
  if (tid < 4) smem[O_BFC + tid] = b_fc[tid];
  for (int idx = tid; idx < 2*HPAR; idx += NTHR) smem[O_H + idx] = 0.f;
  for (int idx = tid; idx < 2*NB*HDIM; idx += NTHR) smem[O_H0C + idx] = 0.f;
  if (tid >= 440 && tid < 448) {
    int b = tid - 440;
    const float* xr = x + (size_t)(g*NB + b) * TSTEPS * 8;
    float* ib = smem + O_INB + b*8;
    ib[0] = 1.f; ib[1] = 1.f; ib[2] = 1.f; ib[3] = 1.f;
    ib[4] = xr[4]; ib[5] = xr[5]; ib[6] = xr[6]; ib[7] = xr[7];
  }
  cluster_sync();

  // per-thread constants (tid < 400)
  const int b = tid & 7, half = (tid >> 3) & 1, j = tid >> 4;
  const int gj = (int)rank*25 + j;
  const unsigned shmask = (tid < 384) ? 0xffffffffu : 0x0000ffffu;

  float4 xnext = make_float4(0.f, 0.f, 0.f, 0.f);

  for (int i = 0; i < TITER; i++) {
    const int p = i & 1, q = p ^ 1;

    // ===== copy phase: derive h0c[p] (lo of pairs) + stage inputs =====
    if (tid < 400 && i <= TSTEPS) {
      int flat = tid * 4;                 // 1600 h0 values
      int cb = flat / HDIM, k0 = flat % HDIM;
      const float* src = smem + O_H + p*HPAR + cb*PITCHP + 2*k0;
      float4 A = *(const float4*)(src);       // {h0 k0, h1, h0 k0+1, h1}
      float4 B = *(const float4*)(src + 4);   // k0+2, k0+3
      float* dst = smem + O_H0C + p*(NB*HDIM) + cb*HDIM + k0;
      *(float4*)dst = make_float4(A.x, A.z, B.x, B.z);
    }
    if (tid >= 440 && tid < 448 && i > 0 && i <= TSTEPS) {
      float* ib = smem + O_INB + (tid - 440)*8;
      ib[0] = xnext.x; ib[1] = xnext.y; ib[2] = xnext.z; ib[3] = xnext.w;
    }
    __syncthreads();

    // ===== main phase =====
    if (tid < 400 && i <= TSTEPS) {
      const float* hp  = smem + O_H   + p*HPAR       + b*PITCHP + half*200;
      const float* h0c = smem + O_H0C + p*(NB*HDIM)  + b*HDIM   + half*100;
      const float* wpr = smem + O_W01 + (     j)*400 + half*200;
      const float* wpz = smem + O_W01 + (25 + j)*400 + half*200;
      const float* wpn = smem + O_W01 + (50 + j)*400 + half*200;
      const float* wsr = smem + O_WM2 + (     j)*HDIM + half*100;
      const float* wsz = smem + O_WM2 + (25 + j)*HDIM + half*100;
      const float* wsn = smem + O_WM2 + (50 + j)*HDIM + half*100;
      u64 pr = 0, pz = 0, pn = 0;
      float sr = 0.f, sz = 0.f, sn = 0.f;
      #pragma unroll
      for (int c = 0; c < 25; c++) {
        const int kk = c*4;
        ulonglong2 Hx = *(const ulonglong2*)(hp + 2*kk);       // k,k+1
        ulonglong2 Hy = *(const ulonglong2*)(hp + 2*kk + 4);   // k+2,k+3
        float4 V = *(const float4*)(h0c + kk);
        ulonglong2 W;
        W = *(const ulonglong2*)(wpr + 2*kk);     FMA2(pr, W.x, Hx.x); FMA2(pr, W.y, Hx.y);
        W = *(const ulonglong2*)(wpr + 2*kk + 4); FMA2(pr, W.x, Hy.x); FMA2(pr, W.y, Hy.y);
        W = *(const ulonglong2*)(wpz + 2*kk);     FMA2(pz, W.x, Hx.x); FMA2(pz, W.y, Hx.y);
        W = *(const ulonglong2*)(wpz + 2*kk + 4); FMA2(pz, W.x, Hy.x); FMA2(pz, W.y, Hy.y);
        W = *(const ulonglong2*)(wpn + 2*kk);     FMA2(pn, W.x, Hx.x); FMA2(pn, W.y, Hx.y);
        W = *(const ulonglong2*)(wpn + 2*kk + 4); FMA2(pn, W.x, Hy.x); FMA2(pn, W.y, Hy.y);
        float4 S;
        S = *(const float4*)(wsr + kk);
        sr = fmaf(S.x, V.x, sr); sr = fmaf(S.y, V.y, sr);
        sr = fmaf(S.z, V.z, sr); sr = fmaf(S.w, V.w, sr);
        S = *(const float4*)(wsz + kk);
        sz = fmaf(S.x, V.x, sz); sz = fmaf(S.y, V.y, sz);
        sz = fmaf(S.z, V.z, sz); sz = fmaf(S.w, V.w, sz);
        S = *(const float4*)(wsn + kk);
        sn = fmaf(S.x, V.x, sn); sn = fmaf(S.y, V.y, sn);
        sn = fmaf(S.z, V.z, sn); sn = fmaf(S.w, V.w, sn);
      }
      // split packed accumulators: lo = Whh0 dot, hi = Whh1 dot
      float h0r, h1r, h0z, h1z, h0n_, h1n_;
      UNPK2(h0r, h1r, pr); UNPK2(h0z, h1z, pz); UNPK2(h0n_, h1n_, pn);
      // combine the two K-halves in-warp (partner = lane ^ 8)
      h0r += __shfl_xor_sync(shmask, h0r, 8);
      h1r += __shfl_xor_sync(shmask, h1r, 8);
      h0z += __shfl_xor_sync(shmask, h0z, 8);
      h1z += __shfl_xor_sync(shmask, h1z, 8);
      h0n_ += __shfl_xor_sync(shmask, h0n_, 8);
      h1n_ += __shfl_xor_sync(shmask, h1n_, 8);
      sr  += __shfl_xor_sync(shmask, sr, 8);
      sz  += __shfl_xor_sync(shmask, sz, 8);
      sn  += __shfl_xor_sync(shmask, sn, 8);

      float h0new = 0.f, h1new = 0.f;
      if (i < TSTEPS) {
        // cell0: ref-step i, layer 0
        float xr = smem[O_B0 + j], xz = smem[O_B0 + 25 + j], xn = smem[O_B0 + 50 + j];
        #pragma unroll
        for (int c = 0; c < 8; c++) {
          float ic = smem[O_INB + b*8 + c];
          xr = fmaf(smem[O_WI0 +       j*8 + c], ic, xr);
          xz = fmaf(smem[O_WI0 + 200 + j*8 + c], ic, xz);
          xn = fmaf(smem[O_WI0 + 400 + j*8 + c], ic, xn);
        }
        float r = sigmoid_f(xr + h0r);
        float z = sigmoid_f(xz + h0z);
        float n = tanh_f(xn + r * (h0n_ + smem[O_B0 + 75 + j]));
        float h_o = smem[O_H + p*HPAR + b*PITCHP + 2*gj];
        h0new = n + z * (h_o - n);
      }
      if (i >= 1) {
        // cell1: ref-step i-1, layer 1 (gx1 = Wih1 . h0^(i) = s*)
        float r = sigmoid_f(sr + h1r + smem[O_B1 + j]);
        float z = sigmoid_f(sz + h1z + smem[O_B1 + 25 + j]);
        float n = tanh_f(sn + smem[O_B1 + 50 + j] +
                         r * (h1n_ + smem[O_B1 + 75 + j]));
        float h_o = smem[O_H + p*HPAR + b*PITCHP + 2*gj + 1];
        h1new = n + z * (h_o - n);
      }
      if (half == 0) {
        u64 pv; PACK2(pv, h0new, h1new);
        uint32_t la = sb + (uint32_t)(O_H + q*HPAR + b*PITCHP + 2*gj) * 4;
        #pragma unroll
        for (int rr = 0; rr < CLSZ; rr++) {
          uint32_t ra;
          asm("mapa.shared::cluster.u32 %0, %1, %2;" : "=r"(ra) : "r"(la), "r"(rr));
          asm volatile("st.shared::cluster.b64 [%0], %1;" :: "r"(ra), "l"(pv) : "memory");
        }
      }
    } else if (tid >= 416 && tid < 420 && i >= 2) {
      // ===== FC: out_{i-2} = tanh(Wfc . h1^(i-1)) ; 4 (o,b) pairs per CTA
      int pidx = (int)rank*4 + (tid - 416);
      int o = pidx >> 3, fb = pidx & 7;
      const float* wf = smem + O_WFC + o*HDIM;
      const float* hv = smem + O_H + p*HPAR + fb*PITCHP;
      float a0 = 0.f, a1 = 0.f, a2 = 0.f, a3 = 0.f;
      #pragma unroll 10
      for (int k = 0; k < HDIM; k += 4) {
        a0 = fmaf(wf[k],   hv[2*k+1], a0);
        a1 = fmaf(wf[k+1], hv[2*k+3], a1);
        a2 = fmaf(wf[k+2], hv[2*k+5], a2);
        a3 = fmaf(wf[k+3], hv[2*k+7], a3);
      }
      float v = tanh_f(a0 + a1 + a2 + a3 + smem[O_BFC + o]);
      out[((size_t)(g*NB + fb) * TSTEPS + (i-2)) * 4 + o] = v;
    }
    // x prefetch for next stage
    if (tid >= 440 && tid < 448 && i < TSTEPS)
      xnext = *(const float4*)(x + ((size_t)(g*NB + (tid-440)) * TSTEPS + i) * 8);

    cluster_sync();
  }
}

extern "C" void kernel_launch(void* const* d_in, const int* in_sizes, int n_in,
                              void* d_out, int out_size) {
  (void)in_sizes; (void)n_in; (void)out_size;
  const float* x     = (const float*)d_in[0];
  const float* W_ih0 = (const float*)d_in[1];
  const float* W_hh0 = (const float*)d_in[2];
  const float* b_ih0 = (const float*)d_in[3];
  const float* b_hh0 = (const float*)d_in[4];
  const float* W_ih1 = (const float*)d_in[5];
  const float* W_hh1 = (const float*)d_in[6];
  const float* b_ih1 = (const float*)d_in[7];
  const float* b_hh1 = (const float*)d_in[8];
  const float* W_fc  = (const float*)d_in[9];
  const float* b_fc  = (const float*)d_in[10];

  cudaFuncSetAttribute(gru2_kernel,
                       cudaFuncAttributeMaxDynamicSharedMemorySize, SMEM_BYTES);
  gru2_kernel<<<128, NTHR, SMEM_BYTES>>>(x, W_ih0, W_hh0, b_ih0, b_hh0,
                                         W_ih1, W_hh1, b_ih1, b_hh1,
                                         W_fc, b_fc, (float*)d_out);
}